// round 2
// baseline (speedup 1.0000x reference)
#include <cuda_runtime.h>

// Problem constants
#define BT    8192      // B*T queries
#define KCB   8192      // codewords per codebook
#define DDIM  128
#define TLEN  1024
#define CCH   256
#define NQ    2097152   // B*C*T quantized elements
#define NIDX  16384     // B*NCB*T indices
#define NITEM 1024      // 2 cb * 64 qtiles * 8 k-eighths

// Scratch (device globals; no allocation allowed)
__device__ float              g_c2[2 * KCB];
__device__ float              g_x2[2 * BT];
__device__ unsigned long long g_key[2 * BT];   // (d2_bits<<32)|k
__device__ double             g_sse;
__device__ int                g_work;

// ---------------------------------------------------------------------------
// packed fp32x2 helpers (Blackwell FFMA2 — only reachable via PTX)
// ---------------------------------------------------------------------------
__device__ __forceinline__ unsigned long long dup2(float x) {
    unsigned long long r;
    asm("mov.b64 %0, {%1, %1};" : "=l"(r) : "f"(x));
    return r;
}
__device__ __forceinline__ void ffma2(unsigned long long& acc,
                                      unsigned long long a,
                                      unsigned long long b) {
    asm("fma.rn.f32x2 %0, %1, %2, %0;" : "+l"(acc) : "l"(a), "l"(b));
}
__device__ __forceinline__ void unpack2(unsigned long long p, float& lo, float& hi) {
    asm("mov.b64 {%0, %1}, %2;" : "=f"(lo), "=f"(hi) : "l"(p));
}

// ---------------------------------------------------------------------------
// init: argmin keys to +inf, counters to 0
// ---------------------------------------------------------------------------
__global__ void init_kernel() {
    int i = blockIdx.x * 1024 + threadIdx.x;
    if (i < 2 * BT) g_key[i] = 0xFFFFFFFFFFFFFFFFull;
    if (i == 0) { g_sse = 0.0; g_work = 0; }
}

// ---------------------------------------------------------------------------
// c2[n*K + k] = sum_d codebooks[n][k][d]^2   (one warp per row)
// ---------------------------------------------------------------------------
__global__ void c2_kernel(const float* __restrict__ cb) {
    int row  = blockIdx.x * 8 + (threadIdx.x >> 5);
    int lane = threadIdx.x & 31;
    float4 v = *reinterpret_cast<const float4*>(cb + (size_t)row * DDIM + lane * 4);
    float s = v.x * v.x + v.y * v.y + v.z * v.z + v.w * v.w;
    #pragma unroll
    for (int o = 16; o; o >>= 1) s += __shfl_down_sync(0xFFFFFFFFu, s, o);
    if (lane == 0) g_c2[row] = s;
}

// ---------------------------------------------------------------------------
// x2[n*BT + bt] = sum_d x[b][n*128+d][t]^2  (coalesced along t)
// ---------------------------------------------------------------------------
__global__ void x2_kernel(const float* __restrict__ x) {
    int bi = blockIdx.x;
    int n  = bi >> 8;
    int b  = (bi >> 5) & 7;
    int t0 = (bi & 31) * 32;
    int tt = threadIdx.x & 31;
    int g  = threadIdx.x >> 5;

    const float* xp = x + ((size_t)b * CCH + (size_t)n * DDIM) * TLEN + t0 + tt;
    float s = 0.f;
    #pragma unroll
    for (int j = 0; j < 16; ++j) {
        float v = xp[(size_t)(g * 16 + j) * TLEN];
        s += v * v;
    }
    __shared__ float sm[8][33];
    sm[g][tt] = s;
    __syncthreads();
    if (threadIdx.x < 32) {
        float tot = 0.f;
        #pragma unroll
        for (int j = 0; j < 8; ++j) tot += sm[j][threadIdx.x];
        g_x2[n * BT + b * TLEN + t0 + threadIdx.x] = tot;
    }
}

// ---------------------------------------------------------------------------
// Persistent fused GEMM+argmin. grid=152 CTAs x 512 threads.
// Work item = (n, qtile, k8): 128 queries x 1024 codewords (8 k-tiles of 128).
// Thread (tx=tid&7, ty=tid>>3): 2 queries {2ty,2ty+1}, 16 codewords
//   k = 4*tx + 32*c + {0..3}, c in 0..3. FFMA2 pairs packed along k.
// ---------------------------------------------------------------------------
#define ROWS  132
#define SMEM_FLOATS (16896 * 2 + 1024 * 2)   // qs + cs + redv + redi

__global__ void __launch_bounds__(512, 1)
vq_kernel(const float* __restrict__ x, const float* __restrict__ cb) {
    extern __shared__ float sm[];
    float* qs   = sm;                 // 128*132
    float* cs   = sm + 16896;         // 128*132
    float* redv = sm + 33792;         // 128*8
    int*   redi = (int*)(sm + 34816); // 128*8
    __shared__ int s_item;

    const int tid = threadIdx.x;
    const int tx  = tid & 7;
    const int ty  = tid >> 3;

    for (;;) {
        if (tid == 0) s_item = atomicAdd(&g_work, 1);
        __syncthreads();
        const int item = s_item;
        if (item >= NITEM) break;

        const int n  = item >> 9;
        const int qt = (item >> 3) & 63;
        const int k8 = item & 7;
        const int qbase = qt * 128;
        const int b  = qbase >> 10;
        const int t0 = qbase & 1023;

        const float* xq  = x  + ((size_t)b * CCH + (size_t)n * DDIM) * TLEN + t0;
        const float* cbn = cb + (size_t)n * KCB * DDIM;

        // ---- load query tile qs[d][t] (coalesced along t) ----
        #pragma unroll
        for (int l = 0; l < 8; ++l) {
            int lin = l * 512 + tid;
            int d   = lin >> 5;
            int t4  = lin & 31;
            float4 v = *reinterpret_cast<const float4*>(xq + (size_t)d * TLEN + t4 * 4);
            *reinterpret_cast<float4*>(qs + d * ROWS + t4 * 4) = v;
        }

        float x2r[2];
        x2r[0] = g_x2[n * BT + qbase + 2 * ty];
        x2r[1] = g_x2[n * BT + qbase + 2 * ty + 1];

        float bestv[2];
        int   bestk[2];
        bestv[0] = bestv[1] = 3.4e38f;
        bestk[0] = bestk[1] = 0;

        for (int tile = 0; tile < 8; ++tile) {
            const int kbase = k8 * 1024 + tile * 128;
            __syncthreads();
            // ---- load codebook tile transposed: cs[d][kk] = cb[kbase+kk][d] ----
            #pragma unroll
            for (int l = 0; l < 8; ++l) {
                int lin = l * 512 + tid;
                int kk  = (lin & 7) | (((lin >> 8) & 15) << 3);
                int d4  = ((lin >> 3) & 3) | (((lin >> 5) & 7) << 2);
                float4 v = *reinterpret_cast<const float4*>(
                    cbn + (size_t)(kbase + kk) * DDIM + d4 * 4);
                cs[(d4 * 4 + 0) * ROWS + kk] = v.x;
                cs[(d4 * 4 + 1) * ROWS + kk] = v.y;
                cs[(d4 * 4 + 2) * ROWS + kk] = v.z;
                cs[(d4 * 4 + 3) * ROWS + kk] = v.w;
            }
            __syncthreads();

            // ---- FFMA2 main loop ----
            unsigned long long acc[2][8];
            #pragma unroll
            for (int i = 0; i < 2; ++i)
                #pragma unroll
                for (int j = 0; j < 8; ++j) acc[i][j] = 0ull;

            #pragma unroll 8
            for (int d = 0; d < 128; ++d) {
                const float2 qp =
                    *reinterpret_cast<const float2*>(qs + d * ROWS + 2 * ty);
                const unsigned long long A0 = dup2(qp.x);
                const unsigned long long A1 = dup2(qp.y);
                const float* crow = cs + d * ROWS + 4 * tx;
                const ulonglong2 B0 = *reinterpret_cast<const ulonglong2*>(crow);
                const ulonglong2 B1 = *reinterpret_cast<const ulonglong2*>(crow + 32);
                const ulonglong2 B2 = *reinterpret_cast<const ulonglong2*>(crow + 64);
                const ulonglong2 B3 = *reinterpret_cast<const ulonglong2*>(crow + 96);
                ffma2(acc[0][0], A0, B0.x); ffma2(acc[0][1], A0, B0.y);
                ffma2(acc[1][0], A1, B0.x); ffma2(acc[1][1], A1, B0.y);
                ffma2(acc[0][2], A0, B1.x); ffma2(acc[0][3], A0, B1.y);
                ffma2(acc[1][2], A1, B1.x); ffma2(acc[1][3], A1, B1.y);
                ffma2(acc[0][4], A0, B2.x); ffma2(acc[0][5], A0, B2.y);
                ffma2(acc[1][4], A1, B2.x); ffma2(acc[1][5], A1, B2.y);
                ffma2(acc[0][6], A0, B3.x); ffma2(acc[0][7], A0, B3.y);
                ffma2(acc[1][6], A1, B3.x); ffma2(acc[1][7], A1, B3.y);
            }

            // ---- epilogue: JAX-exact d2 = (x2 - 2*xc) + c2, running argmin ----
            float4 c2v[4];
            #pragma unroll
            for (int c = 0; c < 4; ++c)
                c2v[c] = __ldg(reinterpret_cast<const float4*>(
                    g_c2 + n * KCB + kbase + 32 * c + 4 * tx));
            #pragma unroll
            for (int i = 0; i < 2; ++i) {
                #pragma unroll
                for (int c = 0; c < 4; ++c) {
                    #pragma unroll
                    for (int h = 0; h < 2; ++h) {
                        float lo, hi;
                        unpack2(acc[i][2 * c + h], lo, hi);
                        int k0 = kbase + 32 * c + 4 * tx + 2 * h;
                        float cA = h ? c2v[c].z : c2v[c].x;
                        float cB = h ? c2v[c].w : c2v[c].y;
                        float d2a = __fadd_rn(__fsub_rn(x2r[i], __fmul_rn(2.0f, lo)), cA);
                        if (d2a < bestv[i]) { bestv[i] = d2a; bestk[i] = k0; }
                        float d2b = __fadd_rn(__fsub_rn(x2r[i], __fmul_rn(2.0f, hi)), cB);
                        if (d2b < bestv[i]) { bestv[i] = d2b; bestk[i] = k0 + 1; }
                    }
                }
            }
        }

        // ---- cross-thread reduce (8 tx lanes per query) + global atomic merge --
        __syncthreads();
        redv[(2 * ty + 0) * 8 + tx] = bestv[0];
        redi[(2 * ty + 0) * 8 + tx] = bestk[0];
        redv[(2 * ty + 1) * 8 + tx] = bestv[1];
        redi[(2 * ty + 1) * 8 + tx] = bestk[1];
        __syncthreads();
        if (tid < 128) {
            float bv = 3.4e38f;
            int   bk = 1 << 30;
            #pragma unroll
            for (int j = 0; j < 8; ++j) {
                float v = redv[tid * 8 + j];
                int   k = redi[tid * 8 + j];
                if (v < bv || (v == bv && k < bk)) { bv = v; bk = k; }
            }
            unsigned long long key =
                ((unsigned long long)__float_as_uint(bv) << 32) |
                (unsigned long long)(unsigned)bk;
            atomicMin(&g_key[n * BT + qbase + tid], key);
        }
    }
}

// ---------------------------------------------------------------------------
// Gather quantized output + indices + commit-loss SSE.
// block = one (n, bt), 128 threads.
// ---------------------------------------------------------------------------
__global__ void gather_kernel(const float* __restrict__ x,
                              const float* __restrict__ cb,
                              float* __restrict__ out) {
    int bi = blockIdx.x;              // n*8192 + bt
    int n  = bi >> 13;
    int bt = bi & 8191;
    int b  = bt >> 10;
    int t  = bt & 1023;
    int k  = (int)(unsigned)(g_key[n * BT + bt] & 0xFFFFFFFFull);
    int i  = threadIdx.x;

    float q = cb[(size_t)n * KCB * DDIM + (size_t)k * DDIM + i];
    size_t oidx = ((size_t)b * CCH + (size_t)n * DDIM + i) * TLEN + t;
    out[oidx] = q;

    float d = x[oidx] - q;
    float s = d * d;
    #pragma unroll
    for (int o = 16; o; o >>= 1) s += __shfl_down_sync(0xFFFFFFFFu, s, o);
    __shared__ float sm4[4];
    if ((i & 31) == 0) sm4[i >> 5] = s;
    __syncthreads();
    if (i == 0) {
        atomicAdd(&g_sse, (double)(sm4[0] + sm4[1] + sm4[2] + sm4[3]));
        out[NQ + ((size_t)b * 2 + n) * TLEN + t] = (float)k;   // indices (B,NCB,T)
    }
}

__global__ void fin_kernel(float* __restrict__ out) {
    out[NQ + NIDX] = (float)(0.25 * g_sse / (double)((long long)BT * DDIM));
}

// ---------------------------------------------------------------------------
extern "C" void kernel_launch(void* const* d_in, const int* in_sizes, int n_in,
                              void* d_out, int out_size) {
    const float* x  = (const float*)d_in[0];
    const float* cb = (const float*)d_in[1];
    float* out = (float*)d_out;

    cudaFuncSetAttribute(vq_kernel,
                         cudaFuncAttributeMaxDynamicSharedMemorySize,
                         SMEM_FLOATS * 4);

    init_kernel<<<16, 1024>>>();
    c2_kernel<<<2048, 256>>>(cb);
    x2_kernel<<<512, 256>>>(x);
    vq_kernel<<<152, 512, SMEM_FLOATS * 4>>>(x, cb);
    gather_kernel<<<16384, 128>>>(x, cb, out);
    fin_kernel<<<1, 1>>>(out);
}

// round 3
// speedup vs baseline: 1.3429x; 1.3429x over previous
#include <cuda_runtime.h>

// Problem constants
#define BT    8192      // B*T queries
#define KCB   8192      // codewords per codebook
#define DDIM  128
#define TLEN  1024
#define CCH   256
#define NQ    2097152   // B*C*T quantized elements
#define NIDX  16384     // B*NCB*T indices

// Scratch (device globals; no allocation allowed)
__device__ float              g_c2[2 * KCB];
__device__ float              g_x2[2 * BT];
__device__ unsigned long long g_key[2 * BT];   // (d2_bits<<32)|k
__device__ double             g_sse;

// ---------------------------------------------------------------------------
// packed fp32x2 helpers (Blackwell FFMA2 — only reachable via PTX)
// ---------------------------------------------------------------------------
__device__ __forceinline__ unsigned long long dup2(float x) {
    unsigned long long r;
    asm("mov.b64 %0, {%1, %1};" : "=l"(r) : "f"(x));
    return r;
}
__device__ __forceinline__ void ffma2(unsigned long long& acc,
                                      unsigned long long a,
                                      unsigned long long b) {
    asm("fma.rn.f32x2 %0, %1, %2, %0;" : "+l"(acc) : "l"(a), "l"(b));
}
__device__ __forceinline__ void unpack2(unsigned long long p, float& lo, float& hi) {
    asm("mov.b64 {%0, %1}, %2;" : "=f"(lo), "=f"(hi) : "l"(p));
}

// ---------------------------------------------------------------------------
// init: argmin keys to +inf, sse to 0
// ---------------------------------------------------------------------------
__global__ void init_kernel() {
    int i = blockIdx.x * 1024 + threadIdx.x;
    if (i < 2 * BT) g_key[i] = 0xFFFFFFFFFFFFFFFFull;
    if (i == 0) g_sse = 0.0;
}

// ---------------------------------------------------------------------------
// c2[n*K + k] = sum_d codebooks[n][k][d]^2   (one warp per row)
// ---------------------------------------------------------------------------
__global__ void c2_kernel(const float* __restrict__ cb) {
    int row  = blockIdx.x * 8 + (threadIdx.x >> 5);
    int lane = threadIdx.x & 31;
    float4 v = *reinterpret_cast<const float4*>(cb + (size_t)row * DDIM + lane * 4);
    float s = v.x * v.x + v.y * v.y + v.z * v.z + v.w * v.w;
    #pragma unroll
    for (int o = 16; o; o >>= 1) s += __shfl_down_sync(0xFFFFFFFFu, s, o);
    if (lane == 0) g_c2[row] = s;
}

// ---------------------------------------------------------------------------
// x2[n*BT + bt] = sum_d x[b][n*128+d][t]^2  (coalesced along t)
// ---------------------------------------------------------------------------
__global__ void x2_kernel(const float* __restrict__ x) {
    int bi = blockIdx.x;
    int n  = bi >> 8;
    int b  = (bi >> 5) & 7;
    int t0 = (bi & 31) * 32;
    int tt = threadIdx.x & 31;
    int g  = threadIdx.x >> 5;

    const float* xp = x + ((size_t)b * CCH + (size_t)n * DDIM) * TLEN + t0 + tt;
    float s = 0.f;
    #pragma unroll
    for (int j = 0; j < 16; ++j) {
        float v = xp[(size_t)(g * 16 + j) * TLEN];
        s += v * v;
    }
    __shared__ float sm[8][33];
    sm[g][tt] = s;
    __syncthreads();
    if (threadIdx.x < 32) {
        float tot = 0.f;
        #pragma unroll
        for (int j = 0; j < 8; ++j) tot += sm[j][threadIdx.x];
        g_x2[n * BT + b * TLEN + t0 + threadIdx.x] = tot;
    }
}

// ---------------------------------------------------------------------------
// Fused GEMM+argmin. grid = 1024 CTAs x 512 threads.
// Block item = (n, qtile, kc): 128 queries x 1024 codewords (4 k-tiles of 256).
// Thread (tx=tid&15, ty=tid>>4): queries {4ty..4ty+3},
//   codewords k = 64*c + 4*tx + {0..3}, c in 0..3 (within the 256-wide tile).
// acc pairs packed along k; accumulation sequential over d (JAX-safe order).
// ---------------------------------------------------------------------------
#define QROWS 132
#define CROWS 260
#define SMEM_FLOATS (128 * QROWS + 128 * CROWS)   // 50176 floats = 200704 B

__global__ void __launch_bounds__(512, 1)
vq_kernel(const float* __restrict__ x, const float* __restrict__ cb) {
    extern __shared__ float sm[];
    float* qs = sm;                 // [d][t]  128 x 132
    float* cs = sm + 128 * QROWS;   // [d][k]  128 x 260

    const int tid = threadIdx.x;
    const int tx  = tid & 15;
    const int ty  = tid >> 4;

    const int item = blockIdx.x;
    const int n  = item >> 9;
    const int qt = (item >> 3) & 63;
    const int kc = item & 7;
    const int qbase = qt * 128;
    const int b  = qbase >> 10;
    const int t0 = qbase & 1023;

    const float* xq  = x  + ((size_t)b * CCH + (size_t)n * DDIM) * TLEN + t0;
    const float* cbn = cb + (size_t)n * KCB * DDIM;

    // ---- load query tile qs[d][t] (coalesced along t) ----
    #pragma unroll
    for (int l = 0; l < 8; ++l) {
        int lin = l * 512 + tid;
        int d   = lin >> 5;
        int t4  = lin & 31;
        float4 v = *reinterpret_cast<const float4*>(xq + (size_t)d * TLEN + t4 * 4);
        *reinterpret_cast<float4*>(qs + d * QROWS + t4 * 4) = v;
    }

    float x2r[4];
    #pragma unroll
    for (int i = 0; i < 4; ++i) x2r[i] = g_x2[n * BT + qbase + 4 * ty + i];

    float bestv[4];
    int   bestk[4];
    #pragma unroll
    for (int i = 0; i < 4; ++i) { bestv[i] = 3.4e38f; bestk[i] = 0; }

    for (int tile = 0; tile < 4; ++tile) {
        const int kbase = kc * 1024 + tile * 256;
        __syncthreads();
        // ---- load codebook tile transposed: cs[d][kk] = cb[kbase+kk][d] ----
        // per step: warp = 8 kk x 4 d4 (2-way STS conflict only)
        #pragma unroll
        for (int l = 0; l < 16; ++l) {
            int lin = l * 512 + tid;
            int kk  = (lin & 7) | ((lin >> 8) << 3);
            int d4  = (lin >> 3) & 31;
            float4 v = *reinterpret_cast<const float4*>(
                cbn + (size_t)(kbase + kk) * DDIM + d4 * 4);
            cs[(d4 * 4 + 0) * CROWS + kk] = v.x;
            cs[(d4 * 4 + 1) * CROWS + kk] = v.y;
            cs[(d4 * 4 + 2) * CROWS + kk] = v.z;
            cs[(d4 * 4 + 3) * CROWS + kk] = v.w;
        }
        __syncthreads();

        // ---- FFMA2 main loop: acc[i][2c+h] = xc pairs, sequential over d ----
        unsigned long long acc[4][8];
        #pragma unroll
        for (int i = 0; i < 4; ++i)
            #pragma unroll
            for (int j = 0; j < 8; ++j) acc[i][j] = 0ull;

        #pragma unroll 2
        for (int d = 0; d < 128; ++d) {
            const float4 qp = *reinterpret_cast<const float4*>(qs + d * QROWS + 4 * ty);
            const float* crow = cs + d * CROWS + 4 * tx;
            const ulonglong2 B0 = *reinterpret_cast<const ulonglong2*>(crow);
            const ulonglong2 B1 = *reinterpret_cast<const ulonglong2*>(crow + 64);
            const ulonglong2 B2 = *reinterpret_cast<const ulonglong2*>(crow + 128);
            const ulonglong2 B3 = *reinterpret_cast<const ulonglong2*>(crow + 192);
            {
                const unsigned long long A = dup2(qp.x);
                ffma2(acc[0][0], A, B0.x); ffma2(acc[0][1], A, B0.y);
                ffma2(acc[0][2], A, B1.x); ffma2(acc[0][3], A, B1.y);
                ffma2(acc[0][4], A, B2.x); ffma2(acc[0][5], A, B2.y);
                ffma2(acc[0][6], A, B3.x); ffma2(acc[0][7], A, B3.y);
            }
            {
                const unsigned long long A = dup2(qp.y);
                ffma2(acc[1][0], A, B0.x); ffma2(acc[1][1], A, B0.y);
                ffma2(acc[1][2], A, B1.x); ffma2(acc[1][3], A, B1.y);
                ffma2(acc[1][4], A, B2.x); ffma2(acc[1][5], A, B2.y);
                ffma2(acc[1][6], A, B3.x); ffma2(acc[1][7], A, B3.y);
            }
            {
                const unsigned long long A = dup2(qp.z);
                ffma2(acc[2][0], A, B0.x); ffma2(acc[2][1], A, B0.y);
                ffma2(acc[2][2], A, B1.x); ffma2(acc[2][3], A, B1.y);
                ffma2(acc[2][4], A, B2.x); ffma2(acc[2][5], A, B2.y);
                ffma2(acc[2][6], A, B3.x); ffma2(acc[2][7], A, B3.y);
            }
            {
                const unsigned long long A = dup2(qp.w);
                ffma2(acc[3][0], A, B0.x); ffma2(acc[3][1], A, B0.y);
                ffma2(acc[3][2], A, B1.x); ffma2(acc[3][3], A, B1.y);
                ffma2(acc[3][4], A, B2.x); ffma2(acc[3][5], A, B2.y);
                ffma2(acc[3][6], A, B3.x); ffma2(acc[3][7], A, B3.y);
            }
        }

        // ---- epilogue: JAX-exact d2 = (x2 - 2*xc) + c2, running argmin ----
        #pragma unroll
        for (int c = 0; c < 4; ++c) {
            const float4 c2v = __ldg(reinterpret_cast<const float4*>(
                g_c2 + n * KCB + kbase + 64 * c + 4 * tx));
            #pragma unroll
            for (int i = 0; i < 4; ++i) {
                float lo, hi;
                unpack2(acc[i][2 * c + 0], lo, hi);
                int k0 = kbase + 64 * c + 4 * tx;
                float d2a = __fadd_rn(__fsub_rn(x2r[i], __fmul_rn(2.0f, lo)), c2v.x);
                if (d2a < bestv[i]) { bestv[i] = d2a; bestk[i] = k0; }
                float d2b = __fadd_rn(__fsub_rn(x2r[i], __fmul_rn(2.0f, hi)), c2v.y);
                if (d2b < bestv[i]) { bestv[i] = d2b; bestk[i] = k0 + 1; }
                unpack2(acc[i][2 * c + 1], lo, hi);
                float d2c = __fadd_rn(__fsub_rn(x2r[i], __fmul_rn(2.0f, lo)), c2v.z);
                if (d2c < bestv[i]) { bestv[i] = d2c; bestk[i] = k0 + 2; }
                float d2d = __fadd_rn(__fsub_rn(x2r[i], __fmul_rn(2.0f, hi)), c2v.w);
                if (d2d < bestv[i]) { bestv[i] = d2d; bestk[i] = k0 + 3; }
            }
        }
    }

    // ---- half-warp shfl reduce over 16 tx lanes, then global atomic merge ----
    #pragma unroll
    for (int i = 0; i < 4; ++i) {
        float bv = bestv[i];
        int   bk = bestk[i];
        #pragma unroll
        for (int off = 8; off; off >>= 1) {
            float ov = __shfl_xor_sync(0xFFFFFFFFu, bv, off);
            int   ok = __shfl_xor_sync(0xFFFFFFFFu, bk, off);
            if (ov < bv || (ov == bv && ok < bk)) { bv = ov; bk = ok; }
        }
        if (tx == 0) {
            unsigned long long key =
                ((unsigned long long)__float_as_uint(bv) << 32) |
                (unsigned long long)(unsigned)bk;
            atomicMin(&g_key[n * BT + qbase + 4 * ty + i], key);
        }
    }
}

// ---------------------------------------------------------------------------
// Gather quantized output + indices + commit-loss SSE.
// block = one (n, bt), 128 threads.
// ---------------------------------------------------------------------------
__global__ void gather_kernel(const float* __restrict__ x,
                              const float* __restrict__ cb,
                              float* __restrict__ out) {
    int bi = blockIdx.x;              // n*8192 + bt
    int n  = bi >> 13;
    int bt = bi & 8191;
    int b  = bt >> 10;
    int t  = bt & 1023;
    int k  = (int)(unsigned)(g_key[n * BT + bt] & 0xFFFFFFFFull);
    int i  = threadIdx.x;

    float q = cb[(size_t)n * KCB * DDIM + (size_t)k * DDIM + i];
    size_t oidx = ((size_t)b * CCH + (size_t)n * DDIM + i) * TLEN + t;
    out[oidx] = q;

    float d = x[oidx] - q;
    float s = d * d;
    #pragma unroll
    for (int o = 16; o; o >>= 1) s += __shfl_down_sync(0xFFFFFFFFu, s, o);
    __shared__ float sm4[4];
    if ((i & 31) == 0) sm4[i >> 5] = s;
    __syncthreads();
    if (i == 0) {
        atomicAdd(&g_sse, (double)(sm4[0] + sm4[1] + sm4[2] + sm4[3]));
        out[NQ + ((size_t)b * 2 + n) * TLEN + t] = (float)k;   // indices (B,NCB,T)
    }
}

__global__ void fin_kernel(float* __restrict__ out) {
    out[NQ + NIDX] = (float)(0.25 * g_sse / (double)((long long)BT * DDIM));
}

// ---------------------------------------------------------------------------
extern "C" void kernel_launch(void* const* d_in, const int* in_sizes, int n_in,
                              void* d_out, int out_size) {
    const float* x  = (const float*)d_in[0];
    const float* cb = (const float*)d_in[1];
    float* out = (float*)d_out;

    cudaFuncSetAttribute(vq_kernel,
                         cudaFuncAttributeMaxDynamicSharedMemorySize,
                         SMEM_FLOATS * 4);

    init_kernel<<<16, 1024>>>();
    c2_kernel<<<2048, 256>>>(cb);
    x2_kernel<<<512, 256>>>(x);
    vq_kernel<<<1024, 512, SMEM_FLOATS * 4>>>(x, cb);
    gather_kernel<<<16384, 128>>>(x, cb, out);
    fin_kernel<<<1, 1>>>(out);
}

// round 6
// speedup vs baseline: 2.2445x; 1.6714x over previous
#include <cuda_runtime.h>
#include <cuda_bf16.h>
#include <cstdint>

// Problem constants
#define BT    8192
#define KCB   8192
#define DDIM  128
#define TLEN  1024
#define CCH   256
#define NQ    2097152
#define NIDX  16384
#define MARGIN 2e-3f

// ---------------------------------------------------------------------------
// Scratch (device globals; no allocation allowed)
// ---------------------------------------------------------------------------
__device__ __align__(16) unsigned g_Ahat[16384 * 192];  // bf16x2 [xh|xh|xl] per (n,bt)
__device__ __align__(16) unsigned g_Bhat[16384 * 192];  // bf16x2 [ch|cl|ch] per (n,k)
__device__ float  g_c2[2 * KCB];
__device__ float  g_x2[2 * BT];
__device__ float  g_v1[2 * BT], g_v2[2 * BT], g_v3[2 * BT];
__device__ int    g_k1[2 * BT], g_k2[2 * BT];
__device__ int    g_idx[2 * BT];
__device__ int    g_flagq[2 * BT];
__device__ int    g_nflag;
__device__ double g_sse;

// ---------------------------------------------------------------------------
// PTX helpers (compute_103-legal only: ldmatrix / mma.sync / cp.async)
// ---------------------------------------------------------------------------
__device__ __forceinline__ uint32_t smem_u32(const void* p) {
    uint32_t a;
    asm("{ .reg .u64 t; cvta.to.shared.u64 t, %1; cvt.u32.u64 %0, t; }"
        : "=r"(a) : "l"(p));
    return a;
}
__device__ __forceinline__ void ldsm4(uint32_t& r0, uint32_t& r1,
                                      uint32_t& r2, uint32_t& r3, uint32_t a) {
    asm volatile("ldmatrix.sync.aligned.m8n8.x4.shared.b16 {%0,%1,%2,%3}, [%4];"
                 : "=r"(r0), "=r"(r1), "=r"(r2), "=r"(r3) : "r"(a));
}
__device__ __forceinline__ void mma_bf16(float* d, uint32_t a0, uint32_t a1,
                                         uint32_t a2, uint32_t a3,
                                         uint32_t b0, uint32_t b1) {
    asm volatile(
        "mma.sync.aligned.m16n8k16.row.col.f32.bf16.bf16.f32 "
        "{%0,%1,%2,%3}, {%4,%5,%6,%7}, {%8,%9}, {%0,%1,%2,%3};"
        : "+f"(d[0]), "+f"(d[1]), "+f"(d[2]), "+f"(d[3])
        : "r"(a0), "r"(a1), "r"(a2), "r"(a3), "r"(b0), "r"(b1));
}
__device__ __forceinline__ void cp_async16(uint32_t dst, const void* src) {
    asm volatile("cp.async.cg.shared.global [%0], [%1], 16;"
                 :: "r"(dst), "l"(src) : "memory");
}
#define CP_COMMIT() asm volatile("cp.async.commit_group;" ::: "memory")
#define CP_WAIT0()  asm volatile("cp.async.wait_group 0;" ::: "memory")

// ---------------------------------------------------------------------------
__global__ void init_kernel() {
    if (blockIdx.x == 0 && threadIdx.x == 0) { g_sse = 0.0; g_nflag = 0; }
}

// c2[n*K+k] = sum_d cb^2  (one warp per row)
__global__ void c2_kernel(const float* __restrict__ cb) {
    int row  = blockIdx.x * 8 + (threadIdx.x >> 5);
    int lane = threadIdx.x & 31;
    float4 v = *reinterpret_cast<const float4*>(cb + (size_t)row * DDIM + lane * 4);
    float s = v.x * v.x + v.y * v.y + v.z * v.z + v.w * v.w;
    #pragma unroll
    for (int o = 16; o; o >>= 1) s += __shfl_down_sync(0xFFFFFFFFu, s, o);
    if (lane == 0) g_c2[row] = s;
}

// x2[n*BT+bt] = sum_d x^2
__global__ void x2_kernel(const float* __restrict__ x) {
    int bi = blockIdx.x;
    int n  = bi >> 8;
    int b  = (bi >> 5) & 7;
    int t0 = (bi & 31) * 32;
    int tt = threadIdx.x & 31;
    int g  = threadIdx.x >> 5;
    const float* xp = x + ((size_t)b * CCH + (size_t)n * DDIM) * TLEN + t0 + tt;
    float s = 0.f;
    #pragma unroll
    for (int j = 0; j < 16; ++j) {
        float v = xp[(size_t)(g * 16 + j) * TLEN];
        s += v * v;
    }
    __shared__ float sm[8][33];
    sm[g][tt] = s;
    __syncthreads();
    if (threadIdx.x < 32) {
        float tot = 0.f;
        #pragma unroll
        for (int j = 0; j < 8; ++j) tot += sm[j][threadIdx.x];
        g_x2[n * BT + b * TLEN + t0 + threadIdx.x] = tot;
    }
}

// bf16 hi/lo packers
__device__ __forceinline__ unsigned pack_hi(float a, float b) {
    unsigned short ha = __bfloat16_as_ushort(__float2bfloat16_rn(a));
    unsigned short hb = __bfloat16_as_ushort(__float2bfloat16_rn(b));
    return (unsigned)ha | ((unsigned)hb << 16);
}
__device__ __forceinline__ unsigned pack_lo(float a, float b) {
    float ra = a - __bfloat162float(__float2bfloat16_rn(a));
    float rb = b - __bfloat162float(__float2bfloat16_rn(b));
    unsigned short la = __bfloat16_as_ushort(__float2bfloat16_rn(ra));
    unsigned short lb = __bfloat16_as_ushort(__float2bfloat16_rn(rb));
    return (unsigned)la | ((unsigned)lb << 16);
}

// split_x: Ahat[(n,bt)][192 u32] = bf16x2 [xh(64) | xh(64) | xl(64)]
__global__ void split_x_kernel(const float* __restrict__ x) {
    extern __shared__ char smraw[];
    float* xs = (float*)smraw;          // [128][132]
    int bi = blockIdx.x;
    int n  = bi >> 6;
    int b  = (bi >> 3) & 7;
    int tc = bi & 7;
    int tt = threadIdx.x;
    const float* xp = x + ((size_t)b * CCH + (size_t)n * DDIM) * TLEN + tc * 128 + tt;
    #pragma unroll 8
    for (int d = 0; d < 128; ++d) xs[d * 132 + tt] = xp[(size_t)d * TLEN];
    __syncthreads();
    for (int it = 0; it < 192; ++it) {
        int lin = it * 128 + tt;
        int r   = lin / 192;
        int w   = lin % 192;
        int bt  = b * TLEN + tc * 128 + r;
        unsigned val;
        if (w < 128) {
            int d0 = 2 * (w & 63);
            val = pack_hi(xs[d0 * 132 + r], xs[(d0 + 1) * 132 + r]);
        } else {
            int d0 = 2 * (w - 128);
            val = pack_lo(xs[d0 * 132 + r], xs[(d0 + 1) * 132 + r]);
        }
        g_Ahat[(size_t)(n * BT + bt) * 192 + w] = val;
    }
}

// split_cb: Bhat[(n,k)][192 u32] = bf16x2 [ch(64) | cl(64) | ch(64)]
__global__ void split_cb_kernel(const float* __restrict__ cb) {
    int row = blockIdx.x;
    int w   = threadIdx.x;
    const float* cp = cb + (size_t)row * DDIM;
    unsigned val;
    if (w < 64) {
        val = pack_hi(cp[2 * w], cp[2 * w + 1]);
    } else if (w < 128) {
        int d0 = 2 * (w - 64);
        val = pack_lo(cp[d0], cp[d0 + 1]);
    } else {
        int d0 = 2 * (w - 128);
        val = pack_hi(cp[d0], cp[d0 + 1]);
    }
    g_Bhat[(size_t)row * 192 + w] = val;
}

// ---------------------------------------------------------------------------
// vq_mma: one CTA per (cb n, 128-query tile). 256 threads, 8 warps (4m x 2n).
// A tile 128q x 384 bf16 resident in smem; B tiles 64 cw x 384 double-buffered
// via cp.async. Warp tile 32q x 32k. Per-thread register top-3 per q-row.
// SMEM (bytes): A @0 (100352), B0 @100352 (50176), B1 @150528 (50176),
//               MV @200704 (12288), MK @212992 (12288) -> total 225280.
// ---------------------------------------------------------------------------
#define RSTRIDE 784          // bytes per smem row (392 halves: 384 data + 8 pad)
#define SM_A    0
#define SM_B0   100352
#define SM_B1   150528
#define SM_MV   200704
#define SM_MK   212992
#define SM_TOT  225280

__global__ void __launch_bounds__(256, 1)
vq_mma_kernel() {
    extern __shared__ char smraw[];
    const uint32_t sb = smem_u32(smraw);
    const int tid  = threadIdx.x;
    const int wid  = tid >> 5;
    const int lane = tid & 31;
    const int gq   = lane >> 2;          // fragment row group 0-7
    const int tq   = lane & 3;           // fragment col pair 0-3
    const int mw   = wid >> 1;           // m-warp 0-3 (32q each)
    const int nw   = wid & 1;            // n-warp 0-1 (32k each)
    const int n    = blockIdx.x >> 6;
    const int qbase = (blockIdx.x & 63) * 128;

    // ---- A tile: 128 rows x 768B (48 x 16B chunks) via cp.async ----
    {
        const char* asrc = (const char*)g_Ahat + (size_t)(n * BT + qbase) * 768;
        #pragma unroll
        for (int it = 0; it < 24; ++it) {
            int c   = it * 256 + tid;
            int row = c / 48, col = c % 48;
            cp_async16(sb + SM_A + row * RSTRIDE + col * 16,
                       asrc + (size_t)row * 768 + col * 16);
        }
    }
    // ---- B tile 0 ----
    const char* bsrc = (const char*)g_Bhat + (size_t)n * KCB * 768;
    #pragma unroll
    for (int it = 0; it < 12; ++it) {
        int c   = it * 256 + tid;
        int row = c / 48, col = c % 48;
        cp_async16(sb + SM_B0 + row * RSTRIDE + col * 16,
                   bsrc + (size_t)row * 768 + col * 16);
    }
    CP_COMMIT();
    CP_WAIT0();
    __syncthreads();

    // ldmatrix lane base addresses
    const uint32_t lmo = (uint32_t)((lane & 15) * RSTRIDE + (lane >> 4) * 16);
    const uint32_t aAddr0 = sb + SM_A + (uint32_t)(mw * 32) * RSTRIDE + lmo;
    const uint32_t aAddr1 = aAddr0 + 16 * RSTRIDE;
    const uint32_t bAddrP[2] = {
        sb + SM_B0 + (uint32_t)(nw * 32) * RSTRIDE + lmo,
        sb + SM_B1 + (uint32_t)(nw * 32) * RSTRIDE + lmo };

    // per-thread top-3 for 4 q-rows: rows (mt, half) -> idx mt*2+half
    float v1[4], v2[4], v3[4];
    int   k1[4], k2[4];
    #pragma unroll
    for (int i = 0; i < 4; ++i) {
        v1[i] = v2[i] = v3[i] = 3.4e38f;
        k1[i] = k2[i] = 0;
    }

    for (int iter = 0; iter < 128; ++iter) {
        const int cur = iter & 1;
        // prefetch next B tile
        if (iter + 1 < 128) {
            const char* src = bsrc + (size_t)(iter + 1) * 64 * 768;
            uint32_t dstb = sb + ((iter + 1) & 1 ? SM_B1 : SM_B0);
            #pragma unroll
            for (int it = 0; it < 12; ++it) {
                int c   = it * 256 + tid;
                int row = c / 48, col = c % 48;
                cp_async16(dstb + row * RSTRIDE + col * 16,
                           src + (size_t)row * 768 + col * 16);
            }
            CP_COMMIT();
        }

        // ---- GEMM: acc[mt][nt][4] over 24 k-steps ----
        float acc[2][4][4];
        #pragma unroll
        for (int mt = 0; mt < 2; ++mt)
            #pragma unroll
            for (int nt = 0; nt < 4; ++nt)
                #pragma unroll
                for (int j = 0; j < 4; ++j) acc[mt][nt][j] = 0.f;

        const uint32_t bA = bAddrP[cur];
        #pragma unroll
        for (int ks = 0; ks < 24; ++ks) {
            uint32_t a0, a1, a2, a3, c0, c1, c2r, c3;
            uint32_t b0x, b1x, b0y, b1y;   // tiles 0,1
            uint32_t b0z, b1z, b0w, b1w;   // tiles 2,3
            ldsm4(a0, a1, a2, a3, aAddr0 + ks * 32);
            ldsm4(c0, c1, c2r, c3, aAddr1 + ks * 32);
            ldsm4(b0x, b0y, b1x, b1y, bA + ks * 32);
            ldsm4(b0z, b0w, b1z, b1w, bA + 16 * RSTRIDE + ks * 32);
            mma_bf16(acc[0][0], a0, a1, a2, a3, b0x, b1x);
            mma_bf16(acc[0][1], a0, a1, a2, a3, b0y, b1y);
            mma_bf16(acc[0][2], a0, a1, a2, a3, b0z, b1z);
            mma_bf16(acc[0][3], a0, a1, a2, a3, b0w, b1w);
            mma_bf16(acc[1][0], c0, c1, c2r, c3, b0x, b1x);
            mma_bf16(acc[1][1], c0, c1, c2r, c3, b0y, b1y);
            mma_bf16(acc[1][2], c0, c1, c2r, c3, b0z, b1z);
            mma_bf16(acc[1][3], c0, c1, c2r, c3, b0w, b1w);
        }

        // ---- epilogue: s = c2[k] - 2*xc, per-row top-3 ----
        const int kbw = iter * 64 + nw * 32;
        #pragma unroll
        for (int nt = 0; nt < 4; ++nt) {
            const int kg = kbw + nt * 8 + tq * 2;
            const float2 c2p = __ldg(reinterpret_cast<const float2*>(
                g_c2 + n * KCB + kg));
            #pragma unroll
            for (int mt = 0; mt < 2; ++mt) {
                #pragma unroll
                for (int half = 0; half < 2; ++half) {
                    const int r = mt * 2 + half;
                    float s0 = fmaf(acc[mt][nt][half * 2 + 0], -2.0f, c2p.x);
                    float s1 = fmaf(acc[mt][nt][half * 2 + 1], -2.0f, c2p.y);
                    if (s0 < v3[r]) {
                        if (s0 < v2[r]) {
                            v3[r] = v2[r];
                            if (s0 < v1[r]) { v2[r] = v1[r]; k2[r] = k1[r];
                                              v1[r] = s0;    k1[r] = kg; }
                            else            { v2[r] = s0;    k2[r] = kg; }
                        } else v3[r] = s0;
                    }
                    if (s1 < v3[r]) {
                        if (s1 < v2[r]) {
                            v3[r] = v2[r];
                            if (s1 < v1[r]) { v2[r] = v1[r]; k2[r] = k1[r];
                                              v1[r] = s1;    k1[r] = kg + 1; }
                            else            { v2[r] = s1;    k2[r] = kg + 1; }
                        } else v3[r] = s1;
                    }
                }
            }
        }

        CP_WAIT0();
        __syncthreads();
    }

    // ---- merge: each (thread, q-row) writes its top-3 into smem ----
    float* MV = (float*)(smraw + SM_MV);
    int*   MK = (int*)(smraw + SM_MK);
    #pragma unroll
    for (int mt = 0; mt < 2; ++mt) {
        #pragma unroll
        for (int half = 0; half < 2; ++half) {
            const int r  = mt * 2 + half;
            const int ql = mw * 32 + mt * 16 + half * 8 + gq;
            const int s0 = ql * 24 + (nw * 4 + tq) * 3;
            MV[s0 + 0] = v1[r]; MK[s0 + 0] = k1[r];
            MV[s0 + 1] = v2[r]; MK[s0 + 1] = k2[r];
            MV[s0 + 2] = v3[r]; MK[s0 + 2] = 0;
        }
    }
    __syncthreads();
    if (tid < 128) {
        float b1 = 3.4e38f, b2 = 3.4e38f, b3 = 3.4e38f;
        int   i1 = 1 << 30, i2 = 1 << 30;
        #pragma unroll 4
        for (int j = 0; j < 24; ++j) {
            float v = MV[tid * 24 + j];
            int   k = MK[tid * 24 + j];
            if (v < b1 || (v == b1 && k < i1)) {
                b3 = b2; b2 = b1; i2 = i1; b1 = v; i1 = k;
            } else if (v < b2 || (v == b2 && k < i2)) {
                b3 = b2; b2 = v; i2 = k;
            } else if (v < b3) b3 = v;
        }
        const int q = n * BT + qbase + tid;
        const float x2v = g_x2[q];
        g_v1[q] = x2v + b1; g_v2[q] = x2v + b2; g_v3[q] = x2v + b3;
        g_k1[q] = i1;       g_k2[q] = i2;
    }
}

// ---------------------------------------------------------------------------
// exact JAX-order d2 (identical arithmetic to rounds 1-3 passing kernels)
// ---------------------------------------------------------------------------
__device__ __forceinline__ float exact_d2(const float* __restrict__ x,
                                          const float* __restrict__ cb,
                                          int n, int b, int t, int bt, int k) {
    const float* xp = x + ((size_t)b * CCH + (size_t)n * DDIM) * TLEN + t;
    const float* cp = cb + ((size_t)n * KCB + (size_t)k) * DDIM;
    float xc = 0.f;
    #pragma unroll 8
    for (int d = 0; d < DDIM; ++d) xc = fmaf(xp[(size_t)d * TLEN], cp[d], xc);
    return __fadd_rn(__fsub_rn(g_x2[n * BT + bt], __fmul_rn(2.0f, xc)),
                     g_c2[n * KCB + k]);
}

// ---------------------------------------------------------------------------
// finalize: certify k1, rescore near-ties, flag ambiguous
// ---------------------------------------------------------------------------
__global__ void finalize_kernel(const float* __restrict__ x,
                                const float* __restrict__ cb,
                                float* __restrict__ out) {
    int q = blockIdx.x * 256 + threadIdx.x;
    int n = q >> 13, bt = q & 8191, b = bt >> 10, t = bt & 1023;
    float v1 = g_v1[q], v2 = g_v2[q], v3 = g_v3[q];
    int   k1 = g_k1[q], k2 = g_k2[q];
    if (v3 - v1 <= MARGIN) {
        int pos = atomicAdd(&g_nflag, 1);
        g_flagq[pos] = q;
        return;
    }
    int kf = k1;
    if (v2 - v1 <= MARGIN) {
        float da = exact_d2(x, cb, n, b, t, bt, k1);
        float db = exact_d2(x, cb, n, b, t, bt, k2);
        if (db < da || (db == da && k2 < k1)) kf = k2;
    }
    g_idx[q] = kf;
    out[NQ + ((size_t)b * 2 + n) * TLEN + t] = (float)kf;
}

// ---------------------------------------------------------------------------
// fallback: exact full scan for flagged queries
// ---------------------------------------------------------------------------
__global__ void fallback_kernel(const float* __restrict__ x,
                                const float* __restrict__ cb,
                                float* __restrict__ out) {
    __shared__ float sv[256];
    __shared__ int   sk[256];
    int nf = g_nflag;
    for (int i = blockIdx.x; i < nf; i += 32) {
        int q = g_flagq[i];
        int n = q >> 13, bt = q & 8191, b = bt >> 10, t = bt & 1023;
        float bv = 3.4e38f;
        int   bk = 1 << 30;
        for (int j = 0; j < 32; ++j) {
            int k = threadIdx.x + j * 256;
            float d2 = exact_d2(x, cb, n, b, t, bt, k);
            if (d2 < bv || (d2 == bv && k < bk)) { bv = d2; bk = k; }
        }
        sv[threadIdx.x] = bv;
        sk[threadIdx.x] = bk;
        __syncthreads();
        for (int o = 128; o; o >>= 1) {
            if (threadIdx.x < o) {
                float ov = sv[threadIdx.x + o];
                int   ok = sk[threadIdx.x + o];
                if (ov < sv[threadIdx.x] ||
                    (ov == sv[threadIdx.x] && ok < sk[threadIdx.x])) {
                    sv[threadIdx.x] = ov; sk[threadIdx.x] = ok;
                }
            }
            __syncthreads();
        }
        if (threadIdx.x == 0) {
            g_idx[q] = sk[0];
            out[NQ + ((size_t)b * 2 + n) * TLEN + t] = (float)sk[0];
        }
        __syncthreads();
    }
}

// ---------------------------------------------------------------------------
// gather quantized output + commit-loss SSE
// ---------------------------------------------------------------------------
__global__ void gather_kernel(const float* __restrict__ x,
                              const float* __restrict__ cb,
                              float* __restrict__ out) {
    int bi = blockIdx.x;
    int n  = bi >> 13;
    int bt = bi & 8191;
    int b  = bt >> 10;
    int t  = bt & 1023;
    int k  = g_idx[n * BT + bt];
    int i  = threadIdx.x;

    float q = cb[(size_t)n * KCB * DDIM + (size_t)k * DDIM + i];
    size_t oidx = ((size_t)b * CCH + (size_t)n * DDIM + i) * TLEN + t;
    out[oidx] = q;

    float d = x[oidx] - q;
    float s = d * d;
    #pragma unroll
    for (int o = 16; o; o >>= 1) s += __shfl_down_sync(0xFFFFFFFFu, s, o);
    __shared__ float sm4[4];
    if ((i & 31) == 0) sm4[i >> 5] = s;
    __syncthreads();
    if (i == 0)
        atomicAdd(&g_sse, (double)(sm4[0] + sm4[1] + sm4[2] + sm4[3]));
}

__global__ void fin_kernel(float* __restrict__ out) {
    out[NQ + NIDX] = (float)(0.25 * g_sse / (double)((long long)BT * DDIM));
}

// ---------------------------------------------------------------------------
extern "C" void kernel_launch(void* const* d_in, const int* in_sizes, int n_in,
                              void* d_out, int out_size) {
    const float* x  = (const float*)d_in[0];
    const float* cb = (const float*)d_in[1];
    float* out = (float*)d_out;

    cudaFuncSetAttribute(vq_mma_kernel,
                         cudaFuncAttributeMaxDynamicSharedMemorySize, SM_TOT);
    cudaFuncSetAttribute(split_x_kernel,
                         cudaFuncAttributeMaxDynamicSharedMemorySize, 128 * 132 * 4);

    init_kernel<<<1, 32>>>();
    c2_kernel<<<2048, 256>>>(cb);
    x2_kernel<<<512, 256>>>(x);
    split_x_kernel<<<128, 128, 128 * 132 * 4>>>(x);
    split_cb_kernel<<<16384, 192>>>(cb);
    vq_mma_kernel<<<128, 256, SM_TOT>>>();
    finalize_kernel<<<64, 256>>>(x, cb, out);
    fallback_kernel<<<32, 256>>>(x, cb, out);
    gather_kernel<<<16384, 128>>>(x, cb, out);
    fin_kernel<<<1, 1>>>(out);
}

// round 7
// speedup vs baseline: 2.2964x; 1.0231x over previous
#include <cuda_runtime.h>
#include <cuda_bf16.h>
#include <cstdint>

// Problem constants
#define BT    8192
#define KCB   8192
#define DDIM  128
#define TLEN  1024
#define CCH   256
#define NQ    2097152
#define NIDX  16384
#define MARGIN 2e-3f

// ---------------------------------------------------------------------------
// Scratch (device globals; no allocation allowed)
// ---------------------------------------------------------------------------
__device__ __align__(16) unsigned g_Ahat[16384 * 192];  // bf16x2 [xh|xh|xl] per (n,bt)
__device__ __align__(16) unsigned g_Bhat[16384 * 192];  // bf16x2 [ch|cl|ch] per (n,k)
__device__ float  g_c2[2 * KCB];
__device__ float  g_x2[2 * BT];
__device__ float  g_v1[2 * BT], g_v2[2 * BT], g_v3[2 * BT];
__device__ int    g_k1[2 * BT], g_k2[2 * BT];
__device__ int    g_idx[2 * BT];
__device__ int    g_flagq[2 * BT];
__device__ int    g_nflag;
__device__ double g_sse;

// ---------------------------------------------------------------------------
// PTX helpers (compute_103-legal only: ldmatrix / mma.sync / cp.async)
// ---------------------------------------------------------------------------
__device__ __forceinline__ uint32_t smem_u32(const void* p) {
    uint32_t a;
    asm("{ .reg .u64 t; cvta.to.shared.u64 t, %1; cvt.u32.u64 %0, t; }"
        : "=r"(a) : "l"(p));
    return a;
}
__device__ __forceinline__ void ldsm4(uint32_t& r0, uint32_t& r1,
                                      uint32_t& r2, uint32_t& r3, uint32_t a) {
    asm volatile("ldmatrix.sync.aligned.m8n8.x4.shared.b16 {%0,%1,%2,%3}, [%4];"
                 : "=r"(r0), "=r"(r1), "=r"(r2), "=r"(r3) : "r"(a));
}
__device__ __forceinline__ void mma_bf16(float* d, uint32_t a0, uint32_t a1,
                                         uint32_t a2, uint32_t a3,
                                         uint32_t b0, uint32_t b1) {
    asm volatile(
        "mma.sync.aligned.m16n8k16.row.col.f32.bf16.bf16.f32 "
        "{%0,%1,%2,%3}, {%4,%5,%6,%7}, {%8,%9}, {%0,%1,%2,%3};"
        : "+f"(d[0]), "+f"(d[1]), "+f"(d[2]), "+f"(d[3])
        : "r"(a0), "r"(a1), "r"(a2), "r"(a3), "r"(b0), "r"(b1));
}
__device__ __forceinline__ void cp_async16(uint32_t dst, const void* src) {
    asm volatile("cp.async.cg.shared.global [%0], [%1], 16;"
                 :: "r"(dst), "l"(src) : "memory");
}
#define CP_COMMIT() asm volatile("cp.async.commit_group;" ::: "memory")
#define CP_WAIT0()  asm volatile("cp.async.wait_group 0;" ::: "memory")
#define CP_WAIT1()  asm volatile("cp.async.wait_group 1;" ::: "memory")

// ---------------------------------------------------------------------------
__global__ void init_kernel() {
    if (blockIdx.x == 0 && threadIdx.x == 0) { g_sse = 0.0; g_nflag = 0; }
}

// c2[n*K+k] = sum_d cb^2  (one warp per row)
__global__ void c2_kernel(const float* __restrict__ cb) {
    int row  = blockIdx.x * 8 + (threadIdx.x >> 5);
    int lane = threadIdx.x & 31;
    float4 v = *reinterpret_cast<const float4*>(cb + (size_t)row * DDIM + lane * 4);
    float s = v.x * v.x + v.y * v.y + v.z * v.z + v.w * v.w;
    #pragma unroll
    for (int o = 16; o; o >>= 1) s += __shfl_down_sync(0xFFFFFFFFu, s, o);
    if (lane == 0) g_c2[row] = s;
}

// x2[n*BT+bt] = sum_d x^2
__global__ void x2_kernel(const float* __restrict__ x) {
    int bi = blockIdx.x;
    int n  = bi >> 8;
    int b  = (bi >> 5) & 7;
    int t0 = (bi & 31) * 32;
    int tt = threadIdx.x & 31;
    int g  = threadIdx.x >> 5;
    const float* xp = x + ((size_t)b * CCH + (size_t)n * DDIM) * TLEN + t0 + tt;
    float s = 0.f;
    #pragma unroll
    for (int j = 0; j < 16; ++j) {
        float v = xp[(size_t)(g * 16 + j) * TLEN];
        s += v * v;
    }
    __shared__ float sm[8][33];
    sm[g][tt] = s;
    __syncthreads();
    if (threadIdx.x < 32) {
        float tot = 0.f;
        #pragma unroll
        for (int j = 0; j < 8; ++j) tot += sm[j][threadIdx.x];
        g_x2[n * BT + b * TLEN + t0 + threadIdx.x] = tot;
    }
}

// bf16 hi/lo packers
__device__ __forceinline__ unsigned pack_hi(float a, float b) {
    unsigned short ha = __bfloat16_as_ushort(__float2bfloat16_rn(a));
    unsigned short hb = __bfloat16_as_ushort(__float2bfloat16_rn(b));
    return (unsigned)ha | ((unsigned)hb << 16);
}
__device__ __forceinline__ unsigned pack_lo(float a, float b) {
    float ra = a - __bfloat162float(__float2bfloat16_rn(a));
    float rb = b - __bfloat162float(__float2bfloat16_rn(b));
    unsigned short la = __bfloat16_as_ushort(__float2bfloat16_rn(ra));
    unsigned short lb = __bfloat16_as_ushort(__float2bfloat16_rn(rb));
    return (unsigned)la | ((unsigned)lb << 16);
}

// split_x: Ahat[(n,bt)][192 u32] = bf16x2 [xh | xh | xl]
// grid 512 = (n:2, b:8, tchunk:32 of 32 t's), block 256.
__global__ void split_x_kernel(const float* __restrict__ x) {
    __shared__ float xs[128 * 33];
    int bi = blockIdx.x;
    int n  = bi >> 8;
    int b  = (bi >> 5) & 7;
    int tc = bi & 31;
    int tid = threadIdx.x;
    int tt  = tid & 31;
    int dg  = tid >> 5;
    const float* xp = x + ((size_t)b * CCH + (size_t)n * DDIM) * TLEN + tc * 32 + tt;
    #pragma unroll
    for (int j = 0; j < 16; ++j) {
        int d = dg * 16 + j;
        xs[d * 33 + tt] = xp[(size_t)d * TLEN];
    }
    __syncthreads();
    // 32 t x 192 words = 6144 words; 24 per thread; writes coalesced along w
    #pragma unroll
    for (int it = 0; it < 24; ++it) {
        int lin = it * 256 + tid;
        int r   = lin / 192;
        int w   = lin % 192;
        int bt  = b * TLEN + tc * 32 + r;
        unsigned val;
        if (w < 128) {
            int d0 = 2 * (w & 63);
            val = pack_hi(xs[d0 * 33 + r], xs[(d0 + 1) * 33 + r]);
        } else {
            int d0 = 2 * (w - 128);
            val = pack_lo(xs[d0 * 33 + r], xs[(d0 + 1) * 33 + r]);
        }
        g_Ahat[(size_t)(n * BT + bt) * 192 + w] = val;
    }
}

// split_cb: Bhat[(n,k)][192 u32] = bf16x2 [ch | cl | ch]
__global__ void split_cb_kernel(const float* __restrict__ cb) {
    int row = blockIdx.x;
    int w   = threadIdx.x;
    const float* cp = cb + (size_t)row * DDIM;
    unsigned val;
    if (w < 64) {
        val = pack_hi(cp[2 * w], cp[2 * w + 1]);
    } else if (w < 128) {
        int d0 = 2 * (w - 64);
        val = pack_lo(cp[d0], cp[d0 + 1]);
    } else {
        int d0 = 2 * (w - 128);
        val = pack_hi(cp[d0], cp[d0 + 1]);
    }
    g_Bhat[(size_t)row * 192 + w] = val;
}

// ---------------------------------------------------------------------------
// vq_mma: one CTA per (cb n, 128-query tile). 256 threads, 8 warps (4m x 2n).
// A tile 128q x 384 bf16 resident in smem; B tiles (64 cw) double-buffered via
// cp.async with TRUE overlap: compute(i) runs while tile(i+1) is in flight;
// prefetch(i+2) issued after compute(i); wait_group 1 blocks only on tile(i+1).
// ---------------------------------------------------------------------------
#define RSTRIDE 784          // bytes per smem row (392 halves: 384 data + 8 pad)
#define SM_A    0
#define SM_B0   100352
#define SM_B1   150528
#define SM_MV   200704
#define SM_MK   212992
#define SM_TOT  225280

__global__ void __launch_bounds__(256, 1)
vq_mma_kernel() {
    extern __shared__ char smraw[];
    const uint32_t sb = smem_u32(smraw);
    const int tid  = threadIdx.x;
    const int wid  = tid >> 5;
    const int lane = tid & 31;
    const int gq   = lane >> 2;
    const int tq   = lane & 3;
    const int mw   = wid >> 1;
    const int nw   = wid & 1;
    const int n    = blockIdx.x >> 6;
    const int qbase = (blockIdx.x & 63) * 128;

    const char* bsrc = (const char*)g_Bhat + (size_t)n * KCB * 768;

    // ---- prologue: group0 = A tile + B tile0 ; group1 = B tile1 ----
    {
        const char* asrc = (const char*)g_Ahat + (size_t)(n * BT + qbase) * 768;
        #pragma unroll
        for (int it = 0; it < 24; ++it) {
            int c   = it * 256 + tid;
            int row = c / 48, col = c % 48;
            cp_async16(sb + SM_A + row * RSTRIDE + col * 16,
                       asrc + (size_t)row * 768 + col * 16);
        }
        #pragma unroll
        for (int it = 0; it < 12; ++it) {
            int c   = it * 256 + tid;
            int row = c / 48, col = c % 48;
            cp_async16(sb + SM_B0 + row * RSTRIDE + col * 16,
                       bsrc + (size_t)row * 768 + col * 16);
        }
        CP_COMMIT();
        #pragma unroll
        for (int it = 0; it < 12; ++it) {
            int c   = it * 256 + tid;
            int row = c / 48, col = c % 48;
            cp_async16(sb + SM_B1 + row * RSTRIDE + col * 16,
                       bsrc + (size_t)(64 + row) * 768 + col * 16);
        }
        CP_COMMIT();
    }
    CP_WAIT1();          // A + tile0 ready; tile1 still in flight
    __syncthreads();

    const uint32_t lmo = (uint32_t)((lane & 15) * RSTRIDE + (lane >> 4) * 16);
    const uint32_t aAddr0 = sb + SM_A + (uint32_t)(mw * 32) * RSTRIDE + lmo;
    const uint32_t aAddr1 = aAddr0 + 16 * RSTRIDE;
    const uint32_t bAddrP[2] = {
        sb + SM_B0 + (uint32_t)(nw * 32) * RSTRIDE + lmo,
        sb + SM_B1 + (uint32_t)(nw * 32) * RSTRIDE + lmo };

    float v1[4], v2[4], v3[4];
    int   k1[4], k2[4];
    #pragma unroll
    for (int i = 0; i < 4; ++i) {
        v1[i] = v2[i] = v3[i] = 3.4e38f;
        k1[i] = k2[i] = 0;
    }

    for (int iter = 0; iter < 128; ++iter) {
        // ---- GEMM on tile iter (buf iter&1) ----
        float acc[2][4][4];
        #pragma unroll
        for (int mt = 0; mt < 2; ++mt)
            #pragma unroll
            for (int nt = 0; nt < 4; ++nt)
                #pragma unroll
                for (int j = 0; j < 4; ++j) acc[mt][nt][j] = 0.f;

        const uint32_t bA = bAddrP[iter & 1];
        #pragma unroll
        for (int ks = 0; ks < 24; ++ks) {
            uint32_t a0, a1, a2, a3, c0, c1, c2r, c3;
            uint32_t b0x, b1x, b0y, b1y;
            uint32_t b0z, b1z, b0w, b1w;
            ldsm4(a0, a1, a2, a3, aAddr0 + ks * 32);
            ldsm4(c0, c1, c2r, c3, aAddr1 + ks * 32);
            ldsm4(b0x, b0y, b1x, b1y, bA + ks * 32);
            ldsm4(b0z, b0w, b1z, b1w, bA + 16 * RSTRIDE + ks * 32);
            mma_bf16(acc[0][0], a0, a1, a2, a3, b0x, b1x);
            mma_bf16(acc[0][1], a0, a1, a2, a3, b0y, b1y);
            mma_bf16(acc[0][2], a0, a1, a2, a3, b0z, b1z);
            mma_bf16(acc[0][3], a0, a1, a2, a3, b0w, b1w);
            mma_bf16(acc[1][0], c0, c1, c2r, c3, b0x, b1x);
            mma_bf16(acc[1][1], c0, c1, c2r, c3, b0y, b1y);
            mma_bf16(acc[1][2], c0, c1, c2r, c3, b0z, b1z);
            mma_bf16(acc[1][3], c0, c1, c2r, c3, b0w, b1w);
        }

        // ---- epilogue: s = c2[k] - 2*xc, per-row top-3 ----
        const int kbw = iter * 64 + nw * 32;
        #pragma unroll
        for (int nt = 0; nt < 4; ++nt) {
            const int kg = kbw + nt * 8 + tq * 2;
            const float2 c2p = __ldg(reinterpret_cast<const float2*>(
                g_c2 + n * KCB + kg));
            #pragma unroll
            for (int mt = 0; mt < 2; ++mt) {
                #pragma unroll
                for (int half = 0; half < 2; ++half) {
                    const int r = mt * 2 + half;
                    float s0 = fmaf(acc[mt][nt][half * 2 + 0], -2.0f, c2p.x);
                    float s1 = fmaf(acc[mt][nt][half * 2 + 1], -2.0f, c2p.y);
                    if (s0 < v3[r]) {
                        if (s0 < v2[r]) {
                            v3[r] = v2[r];
                            if (s0 < v1[r]) { v2[r] = v1[r]; k2[r] = k1[r];
                                              v1[r] = s0;    k1[r] = kg; }
                            else            { v2[r] = s0;    k2[r] = kg; }
                        } else v3[r] = s0;
                    }
                    if (s1 < v3[r]) {
                        if (s1 < v2[r]) {
                            v3[r] = v2[r];
                            if (s1 < v1[r]) { v2[r] = v1[r]; k2[r] = k1[r];
                                              v1[r] = s1;    k1[r] = kg + 1; }
                            else            { v2[r] = s1;    k2[r] = kg + 1; }
                        } else v3[r] = s1;
                    }
                }
            }
        }

        // all warps done reading buf[iter&1] before it is overwritten
        __syncthreads();

        if (iter + 2 < 128) {
            // prefetch tile iter+2 into buf[iter&1]; then wait for tile iter+1
            const char* src = bsrc + (size_t)(iter + 2) * 64 * 768;
            uint32_t dstb = sb + ((iter & 1) ? SM_B1 : SM_B0);
            #pragma unroll
            for (int it = 0; it < 12; ++it) {
                int c   = it * 256 + tid;
                int row = c / 48, col = c % 48;
                cp_async16(dstb + row * RSTRIDE + col * 16,
                           src + (size_t)row * 768 + col * 16);
            }
            CP_COMMIT();
            CP_WAIT1();       // tile iter+1 complete; iter+2 still in flight
        } else {
            CP_WAIT0();       // drain remaining (tile 127)
        }
        __syncthreads();
    }

    // ---- merge per-thread top-3 lists through smem ----
    float* MV = (float*)(smraw + SM_MV);
    int*   MK = (int*)(smraw + SM_MK);
    #pragma unroll
    for (int mt = 0; mt < 2; ++mt) {
        #pragma unroll
        for (int half = 0; half < 2; ++half) {
            const int r  = mt * 2 + half;
            const int ql = mw * 32 + mt * 16 + half * 8 + gq;
            const int s0 = ql * 24 + (nw * 4 + tq) * 3;
            MV[s0 + 0] = v1[r]; MK[s0 + 0] = k1[r];
            MV[s0 + 1] = v2[r]; MK[s0 + 1] = k2[r];
            MV[s0 + 2] = v3[r]; MK[s0 + 2] = 0;
        }
    }
    __syncthreads();
    if (tid < 128) {
        float b1 = 3.4e38f, b2 = 3.4e38f, b3 = 3.4e38f;
        int   i1 = 1 << 30, i2 = 1 << 30;
        #pragma unroll 4
        for (int j = 0; j < 24; ++j) {
            float v = MV[tid * 24 + j];
            int   k = MK[tid * 24 + j];
            if (v < b1 || (v == b1 && k < i1)) {
                b3 = b2; b2 = b1; i2 = i1; b1 = v; i1 = k;
            } else if (v < b2 || (v == b2 && k < i2)) {
                b3 = b2; b2 = v; i2 = k;
            } else if (v < b3) b3 = v;
        }
        const int q = n * BT + qbase + tid;
        const float x2v = g_x2[q];
        g_v1[q] = x2v + b1; g_v2[q] = x2v + b2; g_v3[q] = x2v + b3;
        g_k1[q] = i1;       g_k2[q] = i2;
    }
}

// ---------------------------------------------------------------------------
// exact JAX-order d2 (identical arithmetic to rounds 1-3 passing kernels)
// ---------------------------------------------------------------------------
__device__ __forceinline__ float exact_d2(const float* __restrict__ x,
                                          const float* __restrict__ cb,
                                          int n, int b, int t, int bt, int k) {
    const float* xp = x + ((size_t)b * CCH + (size_t)n * DDIM) * TLEN + t;
    const float* cp = cb + ((size_t)n * KCB + (size_t)k) * DDIM;
    float xc = 0.f;
    #pragma unroll 8
    for (int d = 0; d < DDIM; ++d) xc = fmaf(xp[(size_t)d * TLEN], cp[d], xc);
    return __fadd_rn(__fsub_rn(g_x2[n * BT + bt], __fmul_rn(2.0f, xc)),
                     g_c2[n * KCB + k]);
}

// ---------------------------------------------------------------------------
// finalize: certify k1, rescore near-ties, flag ambiguous
// ---------------------------------------------------------------------------
__global__ void finalize_kernel(const float* __restrict__ x,
                                const float* __restrict__ cb,
                                float* __restrict__ out) {
    int q = blockIdx.x * 256 + threadIdx.x;
    int n = q >> 13, bt = q & 8191, b = bt >> 10, t = bt & 1023;
    float v1 = g_v1[q], v2 = g_v2[q], v3 = g_v3[q];
    int   k1 = g_k1[q], k2 = g_k2[q];
    if (v3 - v1 <= MARGIN) {
        int pos = atomicAdd(&g_nflag, 1);
        g_flagq[pos] = q;
        return;
    }
    int kf = k1;
    if (v2 - v1 <= MARGIN) {
        float da = exact_d2(x, cb, n, b, t, bt, k1);
        float db = exact_d2(x, cb, n, b, t, bt, k2);
        if (db < da || (db == da && k2 < k1)) kf = k2;
    }
    g_idx[q] = kf;
    out[NQ + ((size_t)b * 2 + n) * TLEN + t] = (float)kf;
}

// ---------------------------------------------------------------------------
// fallback: exact full scan for flagged queries
// ---------------------------------------------------------------------------
__global__ void fallback_kernel(const float* __restrict__ x,
                                const float* __restrict__ cb,
                                float* __restrict__ out) {
    __shared__ float sv[256];
    __shared__ int   sk[256];
    int nf = g_nflag;
    for (int i = blockIdx.x; i < nf; i += 32) {
        int q = g_flagq[i];
        int n = q >> 13, bt = q & 8191, b = bt >> 10, t = bt & 1023;
        float bv = 3.4e38f;
        int   bk = 1 << 30;
        for (int j = 0; j < 32; ++j) {
            int k = threadIdx.x + j * 256;
            float d2 = exact_d2(x, cb, n, b, t, bt, k);
            if (d2 < bv || (d2 == bv && k < bk)) { bv = d2; bk = k; }
        }
        sv[threadIdx.x] = bv;
        sk[threadIdx.x] = bk;
        __syncthreads();
        for (int o = 128; o; o >>= 1) {
            if (threadIdx.x < o) {
                float ov = sv[threadIdx.x + o];
                int   ok = sk[threadIdx.x + o];
                if (ov < sv[threadIdx.x] ||
                    (ov == sv[threadIdx.x] && ok < sk[threadIdx.x])) {
                    sv[threadIdx.x] = ov; sk[threadIdx.x] = ok;
                }
            }
            __syncthreads();
        }
        if (threadIdx.x == 0) {
            g_idx[q] = sk[0];
            out[NQ + ((size_t)b * 2 + n) * TLEN + t] = (float)sk[0];
        }
        __syncthreads();
    }
}

// ---------------------------------------------------------------------------
// gather quantized output + commit-loss SSE
// ---------------------------------------------------------------------------
__global__ void gather_kernel(const float* __restrict__ x,
                              const float* __restrict__ cb,
                              float* __restrict__ out) {
    int bi = blockIdx.x;
    int n  = bi >> 13;
    int bt = bi & 8191;
    int b  = bt >> 10;
    int t  = bt & 1023;
    int k  = g_idx[n * BT + bt];
    int i  = threadIdx.x;

    float q = cb[(size_t)n * KCB * DDIM + (size_t)k * DDIM + i];
    size_t oidx = ((size_t)b * CCH + (size_t)n * DDIM + i) * TLEN + t;
    out[oidx] = q;

    float d = x[oidx] - q;
    float s = d * d;
    #pragma unroll
    for (int o = 16; o; o >>= 1) s += __shfl_down_sync(0xFFFFFFFFu, s, o);
    __shared__ float sm4[4];
    if ((i & 31) == 0) sm4[i >> 5] = s;
    __syncthreads();
    if (i == 0)
        atomicAdd(&g_sse, (double)(sm4[0] + sm4[1] + sm4[2] + sm4[3]));
}

__global__ void fin_kernel(float* __restrict__ out) {
    out[NQ + NIDX] = (float)(0.25 * g_sse / (double)((long long)BT * DDIM));
}

// ---------------------------------------------------------------------------
extern "C" void kernel_launch(void* const* d_in, const int* in_sizes, int n_in,
                              void* d_out, int out_size) {
    const float* x  = (const float*)d_in[0];
    const float* cb = (const float*)d_in[1];
    float* out = (float*)d_out;

    cudaFuncSetAttribute(vq_mma_kernel,
                         cudaFuncAttributeMaxDynamicSharedMemorySize, SM_TOT);

    init_kernel<<<1, 32>>>();
    c2_kernel<<<2048, 256>>>(cb);
    x2_kernel<<<512, 256>>>(x);
    split_x_kernel<<<512, 256>>>(x);
    split_cb_kernel<<<16384, 192>>>(cb);
    vq_mma_kernel<<<128, 256, SM_TOT>>>();
    finalize_kernel<<<64, 256>>>(x, cb, out);
    fallback_kernel<<<32, 256>>>(x, cb, out);
    gather_kernel<<<16384, 128>>>(x, cb, out);
    fin_kernel<<<1, 1>>>(out);
}